// round 3
// baseline (speedup 1.0000x reference)
#include <cuda_runtime.h>
#include <math.h>

// Problem constants
#define BATCH 4
#define SEQ   4096
#define EMB   1024
#define HS    64

#define NSPL  2            // split-K factor for attention
#define BQ    128          // queries per block
#define BK    64           // keys per tile
#define NQT   (SEQ / BQ)   // 32 q-tiles per batch

// ---------------- scratch (allocation-free rule: __device__ globals) ----------
__device__ float g_Q[BATCH * SEQ * HS];
__device__ float g_K[BATCH * SEQ * HS];
__device__ float g_V[BATCH * SEQ * HS];
__device__ float g_opart[NSPL * BATCH * SEQ * HS];   // unnormalized partial O
__device__ float g_m[NSPL][BATCH * SEQ];
__device__ float g_l[NSPL][BATCH * SEQ];

// ---------------- packed f32x2 helpers (FFMA2: 2x fp32 FMA rate on sm_103a) --
typedef unsigned long long u64t;

__device__ __forceinline__ u64t pk2(float lo, float hi) {
    u64t r;
    asm("mov.b64 %0, {%1, %2};" : "=l"(r) : "f"(lo), "f"(hi));
    return r;
}
__device__ __forceinline__ void upk2(u64t v, float& lo, float& hi) {
    asm("mov.b64 {%0, %1}, %2;" : "=f"(lo), "=f"(hi) : "l"(v));
}
__device__ __forceinline__ u64t fma2(u64t a, u64t b, u64t c) {
    u64t d;
    asm("fma.rn.f32x2 %0, %1, %2, %3;" : "=l"(d) : "l"(a), "l"(b), "l"(c));
    return d;
}
__device__ __forceinline__ u64t mul2(u64t a, u64t b) {
    u64t d;
    asm("mul.rn.f32x2 %0, %1, %2;" : "=l"(d) : "l"(a), "l"(b));
    return d;
}

// ============================================================================
// Kernel 1: fused QKV projection.  [M=16384, K=1024] x [1024, 192] tiled GEMM.
// BM=128, BK=16, N=192. 256 threads in 16(tx) x 16(ty); each thread computes an
// 8x12 microtile via 48 FFMA2 per k-element against 8 scalar + 6 u64 smem loads
// (FMA-issue-bound by design, LDS issue ~0.83x of it).
// ============================================================================
#define PBM 128
#define PBK 16
#define PN  192

__global__ __launch_bounds__(256) void proj_kernel(
    const float* __restrict__ x,
    const float* __restrict__ Wq,
    const float* __restrict__ Wk,
    const float* __restrict__ Wv)
{
    __shared__ float xs[PBM][PBK + 1];   // 8.5KB, +1 pad for column reads
    __shared__ float ws[PBK][PN];        // 12KB

    const int tid = threadIdx.x;
    const int tx  = tid & 15;            // 12-col group
    const int ty  = tid >> 4;            // 8-row group
    const int row0 = blockIdx.x * PBM;

    u64t acc2[8][6];
    #pragma unroll
    for (int i = 0; i < 8; i++)
        #pragma unroll
        for (int j = 0; j < 6; j++)
            acc2[i][j] = 0ull;

    for (int kk = 0; kk < EMB; kk += PBK) {
        // x tile: 128 x 16 = 512 float4, two per thread
        #pragma unroll
        for (int t = tid; t < (PBM * PBK) / 4; t += 256) {
            const int r  = t >> 2;
            const int c4 = t & 3;
            const float4 v = *(const float4*)&x[(size_t)(row0 + r) * EMB + kk + c4 * 4];
            xs[r][c4 * 4 + 0] = v.x;
            xs[r][c4 * 4 + 1] = v.y;
            xs[r][c4 * 4 + 2] = v.z;
            xs[r][c4 * 4 + 3] = v.w;
        }
        // W tile: 16 x 192 = 768 float4, three per thread
        #pragma unroll
        for (int t = tid; t < (PBK * PN) / 4; t += 256) {
            const int r  = t / (PN / 4);
            const int cc = (t % (PN / 4)) * 4;
            const float* src;
            if (cc < 64)       src = &Wq[(size_t)(kk + r) * HS + cc];
            else if (cc < 128) src = &Wk[(size_t)(kk + r) * HS + (cc - 64)];
            else               src = &Wv[(size_t)(kk + r) * HS + (cc - 128)];
            *(float4*)&ws[r][cc] = *(const float4*)src;
        }
        __syncthreads();

        #pragma unroll
        for (int k = 0; k < PBK; k++) {
            u64t aa[8], bb[6];
            #pragma unroll
            for (int i = 0; i < 8; i++) {
                const float a = xs[ty * 8 + i][k];
                aa[i] = pk2(a, a);
            }
            #pragma unroll
            for (int j = 0; j < 6; j++)
                bb[j] = *(const u64t*)&ws[k][tx * 12 + 2 * j];
            #pragma unroll
            for (int i = 0; i < 8; i++)
                #pragma unroll
                for (int j = 0; j < 6; j++)
                    acc2[i][j] = fma2(aa[i], bb[j], acc2[i][j]);
        }
        __syncthreads();
    }

    // scatter pairs (pair never straddles a 64-col segment boundary: c even)
    #pragma unroll
    for (int i = 0; i < 8; i++) {
        const size_t r = (size_t)(row0 + ty * 8 + i);
        #pragma unroll
        for (int j = 0; j < 6; j++) {
            const int c = tx * 12 + 2 * j;
            float* dst;
            if (c < 64)       dst = &g_Q[r * HS + c];
            else if (c < 128) dst = &g_K[r * HS + (c - 64)];
            else              dst = &g_V[r * HS + (c - 128)];
            *(u64t*)dst = acc2[i][j];
        }
    }
}

// ============================================================================
// Kernel 2: causal flash attention with split-K (flash-decoding).
// Grid: (q-tile, split, batch). 128 threads = 1 thread per query row.
// q and o live in packed f32x2 registers; K/V tiles in smem; raw scores staged
// per-thread in smem. Each split handles half the K-tiles; combine merges.
// ============================================================================
__global__ __launch_bounds__(128) void attn_kernel()
{
    extern __shared__ float sm[];
    float* Ks = sm;                 // BK*HS  = 4096 floats (16KB)
    float* Vs = sm + BK * HS;       // BK*HS  = 4096 floats (16KB)
    float* ss = sm + 2 * BK * HS;   // BK*BQ  = 8192 floats (32KB)

    const int tid = threadIdx.x;
    const int j   = blockIdx.x;     // q-tile
    const int sp  = blockIdx.y;     // split
    const int b   = blockIdx.z;     // batch
    const int q0  = j * BQ;
    const int q   = q0 + tid;

    const int nkt = 2 * (j + 1);    // K-tiles covering [0, BQ*(j+1))
    const int n0  = nkt / 2;
    const int t0  = sp ? n0  : 0;
    const int t1  = sp ? nkt : n0;

    const float* __restrict__ Kb = g_K + (size_t)b * SEQ * HS;
    const float* __restrict__ Vb = g_V + (size_t)b * SEQ * HS;

    // q row -> 32 packed f32x2 registers
    u64t qq[32];
    {
        const ulonglong2* Qp =
            (const ulonglong2*)(g_Q + ((size_t)b * SEQ + q) * HS);
        #pragma unroll
        for (int i = 0; i < 16; i++) {
            const ulonglong2 t = Qp[i];
            qq[2 * i]     = t.x;
            qq[2 * i + 1] = t.y;
        }
    }

    u64t o2[32];
    #pragma unroll
    for (int i = 0; i < 32; i++) o2[i] = 0ull;
    float m = -INFINITY;
    float l = 0.f;

    for (int kt = t0; kt < t1; kt++) {
        const int k0 = kt * BK;

        // ---- load K/V tiles: 1024 float4 each, 8 per thread ----
        #pragma unroll
        for (int t = tid; t < (BK * HS) / 4; t += BQ) {
            const int r = t >> 4;
            const int c = t & 15;
            ((float4*)Ks)[t] = *(const float4*)&Kb[(size_t)(k0 + r) * HS + 4 * c];
            ((float4*)Vs)[t] = *(const float4*)&Vb[(size_t)(k0 + r) * HS + 4 * c];
        }
        __syncthreads();

        // ---- score pass: 4 keys in flight, packed FMA ----
        float tmax = -INFINITY;
        for (int k = 0; k < BK; k += 4) {
            const ulonglong2* K0 = (const ulonglong2*)&Ks[(k + 0) * HS];
            const ulonglong2* K1 = (const ulonglong2*)&Ks[(k + 1) * HS];
            const ulonglong2* K2 = (const ulonglong2*)&Ks[(k + 2) * HS];
            const ulonglong2* K3 = (const ulonglong2*)&Ks[(k + 3) * HS];
            u64t a0 = 0ull, a1 = 0ull, a2 = 0ull, a3 = 0ull;
            #pragma unroll
            for (int i = 0; i < 16; i++) {
                const ulonglong2 k0v = K0[i], k1v = K1[i], k2v = K2[i], k3v = K3[i];
                a0 = fma2(qq[2 * i], k0v.x, a0); a0 = fma2(qq[2 * i + 1], k0v.y, a0);
                a1 = fma2(qq[2 * i], k1v.x, a1); a1 = fma2(qq[2 * i + 1], k1v.y, a1);
                a2 = fma2(qq[2 * i], k2v.x, a2); a2 = fma2(qq[2 * i + 1], k2v.y, a2);
                a3 = fma2(qq[2 * i], k3v.x, a3); a3 = fma2(qq[2 * i + 1], k3v.y, a3);
            }
            float lo, hi, s0, s1, s2, s3;
            upk2(a0, lo, hi); s0 = (lo + hi) * 0.125f;
            upk2(a1, lo, hi); s1 = (lo + hi) * 0.125f;
            upk2(a2, lo, hi); s2 = (lo + hi) * 0.125f;
            upk2(a3, lo, hi); s3 = (lo + hi) * 0.125f;
            if (k0 + k + 0 > q) s0 = -INFINITY;
            if (k0 + k + 1 > q) s1 = -INFINITY;
            if (k0 + k + 2 > q) s2 = -INFINITY;
            if (k0 + k + 3 > q) s3 = -INFINITY;
            ss[(k + 0) * BQ + tid] = s0;
            ss[(k + 1) * BQ + tid] = s1;
            ss[(k + 2) * BQ + tid] = s2;
            ss[(k + 3) * BQ + tid] = s3;
            tmax = fmaxf(tmax, fmaxf(fmaxf(s0, s1), fmaxf(s2, s3)));
        }

        // ---- online softmax rescale (guarded: m == -inf while o == 0) ----
        const float mnew = fmaxf(m, tmax);
        const float corr = (m == -INFINITY) ? 0.f : __expf(m - mnew);
        l *= corr;
        const u64t cc = pk2(corr, corr);
        #pragma unroll
        for (int i = 0; i < 32; i++) o2[i] = mul2(o2[i], cc);
        m = mnew;

        // ---- P@V accumulate, packed FMA ----
        #pragma unroll 4
        for (int k = 0; k < BK; k++) {
            const float sval = ss[k * BQ + tid];
            // guard: fully-masked tile has m == -inf; exp(-inf - -inf) = NaN
            const float p = (sval == -INFINITY) ? 0.f : __expf(sval - m);
            l += p;
            const u64t pp = pk2(p, p);
            const ulonglong2* V2 = (const ulonglong2*)&Vs[k * HS];
            #pragma unroll
            for (int i = 0; i < 16; i++) {
                const ulonglong2 vv = V2[i];
                o2[2 * i]     = fma2(pp, vv.x, o2[2 * i]);
                o2[2 * i + 1] = fma2(pp, vv.y, o2[2 * i + 1]);
            }
        }
        __syncthreads();
    }

    // ---- write partial (o_hat, m, l) ----
    const size_t qi = (size_t)b * SEQ + q;
    g_m[sp][qi] = m;
    g_l[sp][qi] = l;
    u64t* op = (u64t*)(g_opart + ((size_t)sp * BATCH * SEQ + qi) * (size_t)HS);
    #pragma unroll
    for (int i = 0; i < 32; i++) op[i] = o2[i];
}

// ============================================================================
// Kernel 3: combine the two split-K partials and normalize.
// One thread per query row (16384 threads).
// ============================================================================
__global__ __launch_bounds__(128) void combine_kernel(float* __restrict__ out)
{
    const int idx = blockIdx.x * blockDim.x + threadIdx.x;   // query row
    const float m1 = g_m[0][idx], m2 = g_m[1][idx];
    const float l1 = g_l[0][idx], l2 = g_l[1][idx];
    const float M  = fmaxf(m1, m2);
    const float w1 = (m1 == -INFINITY) ? 0.f : __expf(m1 - M);
    const float w2 = (m2 == -INFINITY) ? 0.f : __expf(m2 - M);
    const float inv = 1.f / (w1 * l1 + w2 * l2);
    const float a = w1 * inv, c = w2 * inv;

    const float4* p1 = (const float4*)(g_opart + (size_t)idx * HS);
    const float4* p2 = (const float4*)(g_opart +
                        ((size_t)BATCH * SEQ + idx) * (size_t)HS);
    float4* po = (float4*)(out + (size_t)idx * HS);
    #pragma unroll
    for (int i = 0; i < 16; i++) {
        const float4 u = p1[i];
        const float4 v = p2[i];
        po[i] = make_float4(u.x * a + v.x * c,
                            u.y * a + v.y * c,
                            u.z * a + v.z * c,
                            u.w * a + v.w * c);
    }
}

// ============================================================================
// Launch
// ============================================================================
extern "C" void kernel_launch(void* const* d_in, const int* in_sizes, int n_in,
                              void* d_out, int out_size)
{
    const float* x  = (const float*)d_in[0];
    const float* Wq = (const float*)d_in[1];
    const float* Wk = (const float*)d_in[2];
    const float* Wv = (const float*)d_in[3];
    float* out = (float*)d_out;

    proj_kernel<<<(BATCH * SEQ) / PBM, 256>>>(x, Wq, Wk, Wv);

    cudaFuncSetAttribute(attn_kernel,
                         cudaFuncAttributeMaxDynamicSharedMemorySize, 65536);
    dim3 agrid(NQT, NSPL, BATCH);
    attn_kernel<<<agrid, BQ, 65536>>>();

    combine_kernel<<<(BATCH * SEQ) / 128, 128>>>(out);
}

// round 11
// speedup vs baseline: 1.4942x; 1.4942x over previous
#include <cuda_runtime.h>
#include <math.h>

// Problem constants
#define BATCH 4
#define SEQ   4096
#define EMB   1024
#define HS    64

#define NSPL  8            // split-K factor for attention
#define BQ    128          // queries per block
#define BK    64           // keys per tile
#define NQT   (SEQ / BQ)   // 32 q-tiles per batch

// ---------------- scratch (allocation-free rule: __device__ globals) ----------
__device__ float g_Q[BATCH * SEQ * HS];
__device__ float g_K[BATCH * SEQ * HS];
__device__ float g_V[BATCH * SEQ * HS];
__device__ float g_opart[NSPL * BATCH * SEQ * HS];   // unnormalized partial O
__device__ float g_m[NSPL][BATCH * SEQ];
__device__ float g_l[NSPL][BATCH * SEQ];

// ---------------- packed f32x2 helpers (FFMA2: 2x fp32 FMA rate on sm_103a) --
typedef unsigned long long u64t;

__device__ __forceinline__ u64t pk2(float lo, float hi) {
    u64t r;
    asm("mov.b64 %0, {%1, %2};" : "=l"(r) : "f"(lo), "f"(hi));
    return r;
}
__device__ __forceinline__ void upk2(u64t v, float& lo, float& hi) {
    asm("mov.b64 {%0, %1}, %2;" : "=f"(lo), "=f"(hi) : "l"(v));
}
__device__ __forceinline__ u64t fma2(u64t a, u64t b, u64t c) {
    u64t d;
    asm("fma.rn.f32x2 %0, %1, %2, %3;" : "=l"(d) : "l"(a), "l"(b), "l"(c));
    return d;
}
__device__ __forceinline__ u64t mul2(u64t a, u64t b) {
    u64t d;
    asm("mul.rn.f32x2 %0, %1, %2;" : "=l"(d) : "l"(a), "l"(b));
    return d;
}

// ---------------- cp.async helpers ------------------------------------------
__device__ __forceinline__ void cpasync16(unsigned dst, const void* src) {
    asm volatile("cp.async.cg.shared.global [%0], [%1], 16;" :: "r"(dst), "l"(src));
}
__device__ __forceinline__ void cpasync_commit() {
    asm volatile("cp.async.commit_group;");
}
__device__ __forceinline__ void cpasync_wait0() {
    asm volatile("cp.async.wait_group 0;");
}

// ============================================================================
// Kernel 1: fused QKV projection.  [M=16384, K=1024] x [1024, 192] tiled GEMM.
// BM=64, BK=16, N=192. 256 threads; 4x12 microtile (24 FFMA2/k/thread).
// Thread tx owns columns {32*j + 2*tx, +1 : j=0..5}: the 6 LDS.64 W-operand
// loads hit bank pair (2tx, 2tx+1), conflict-free with cross-ty broadcast.
// Double-buffered smem: W via cp.async, x via register prefetch, ONE
// __syncthreads per k-tile. __launch_bounds__(256,2) -> 2 CTAs/SM.
// ============================================================================
#define PBM 64
#define PBK 16
#define PN  192
#define PNT (EMB / PBK)    // 64 k-tiles

__global__ __launch_bounds__(256, 2) void proj_kernel(
    const float* __restrict__ x,
    const float* __restrict__ Wq,
    const float* __restrict__ Wk,
    const float* __restrict__ Wv)
{
    __shared__ float xs[2][PBM][PBK + 1];   // 8.7KB (+1 pad for column reads)
    __shared__ float ws[2][PBK * PN];       // 24.6KB

    const int tid  = threadIdx.x;
    const int tx   = tid & 15;              // column group (interleaved)
    const int ty   = tid >> 4;              // 4-row group
    const int row0 = blockIdx.x * PBM;

    // x tile: 64x16 = 256 float4, one per thread
    const int xr = tid >> 2;
    const int xc = tid & 3;
    const float* xsrc = &x[(size_t)(row0 + xr) * EMB + xc * 4];

    // W tile: 16x192 = 768 float4, three cp.asyncs per thread
    const float* wsrc[3];
    unsigned     wdst[3];
    #pragma unroll
    for (int p = 0; p < 3; p++) {
        const int t  = tid + p * 256;
        const int r  = t / (PN / 4);
        const int cc = (t % (PN / 4)) * 4;
        const float* s;
        if (cc < 64)       s = &Wq[(size_t)r * HS + cc];
        else if (cc < 128) s = &Wk[(size_t)r * HS + (cc - 64)];
        else               s = &Wv[(size_t)r * HS + (cc - 128)];
        wsrc[p] = s;
        wdst[p] = (unsigned)(r * PN + cc);  // float index within a ws buffer
    }
    const unsigned ws0 = (unsigned)__cvta_generic_to_shared(&ws[0][0]);
    const unsigned ws1 = (unsigned)__cvta_generic_to_shared(&ws[1][0]);

    u64t acc2[4][6];
    #pragma unroll
    for (int i = 0; i < 4; i++)
        #pragma unroll
        for (int j = 0; j < 6; j++)
            acc2[i][j] = 0ull;

    // ---- prologue: tile 0 into buffer 0 ----
    {
        const float4 v = *(const float4*)xsrc;
        xs[0][xr][xc * 4 + 0] = v.x;
        xs[0][xr][xc * 4 + 1] = v.y;
        xs[0][xr][xc * 4 + 2] = v.z;
        xs[0][xr][xc * 4 + 3] = v.w;
        #pragma unroll
        for (int p = 0; p < 3; p++)
            cpasync16(ws0 + wdst[p] * 4, wsrc[p]);
        cpasync_commit();
        cpasync_wait0();
    }
    __syncthreads();

    for (int i = 0; i < PNT; i++) {
        const int buf = i & 1;
        const unsigned wsn = (buf ? ws0 : ws1);   // next buffer's smem base
        float4 xreg;
        const bool more = (i + 1 < PNT);
        if (more) {
            // Prefetch tile i+1 into buffer buf^1 (its readers retired at the
            // barrier ending iteration i-1).
            xreg = *(const float4*)(xsrc + (size_t)(i + 1) * PBK);
            #pragma unroll
            for (int p = 0; p < 3; p++)
                cpasync16(wsn + wdst[p] * 4,
                          wsrc[p] + (size_t)(i + 1) * PBK * HS);
            cpasync_commit();
        }

        // ---- compute on current buffer ----
        const float* wsf = &ws[buf][0];
        #pragma unroll
        for (int k = 0; k < PBK; k++) {
            u64t aa[4], bb[6];
            #pragma unroll
            for (int r4 = 0; r4 < 4; r4++) {
                const float a = xs[buf][ty * 4 + r4][k];
                aa[r4] = pk2(a, a);
            }
            #pragma unroll
            for (int j = 0; j < 6; j++)
                bb[j] = *(const u64t*)&wsf[k * PN + 32 * j + 2 * tx];
            #pragma unroll
            for (int r4 = 0; r4 < 4; r4++)
                #pragma unroll
                for (int j = 0; j < 6; j++)
                    acc2[r4][j] = fma2(aa[r4], bb[j], acc2[r4][j]);
        }

        if (more) {
            const int nb = buf ^ 1;
            xs[nb][xr][xc * 4 + 0] = xreg.x;
            xs[nb][xr][xc * 4 + 1] = xreg.y;
            xs[nb][xr][xc * 4 + 2] = xreg.z;
            xs[nb][xr][xc * 4 + 3] = xreg.w;
            cpasync_wait0();                   // next W tile landed (overlapped)
        }
        __syncthreads();   // single barrier: publish xs/ws, retire reads of buf
    }

    // ---- scatter: column c = 32*j + 2*tx (+1). j=0,1 -> Q; 2,3 -> K; 4,5 -> V
    #pragma unroll
    for (int r4 = 0; r4 < 4; r4++) {
        const size_t r = (size_t)(row0 + ty * 4 + r4);
        #pragma unroll
        for (int j = 0; j < 6; j++) {
            const int c = 32 * j + 2 * tx;
            float* dst;
            if (j < 2)      dst = &g_Q[r * HS + c];
            else if (j < 4) dst = &g_K[r * HS + (c - 64)];
            else            dst = &g_V[r * HS + (c - 128)];
            *(u64t*)dst = acc2[r4][j];
        }
    }
}

// ============================================================================
// Kernel 2: causal flash attention with split-K (flash-decoding).
// Grid: (q-tile, split, batch). 128 threads = 1 thread per query row.
// __launch_bounds__(128,3): 3 CTAs/SM (12 warps). NSPL=8 splits of <=8
// K-tiles; q-tile index reversed so heaviest blocks are scheduled first
// (LPT -> smaller makespan). combine merges 8 partials.
// ============================================================================
__global__ __launch_bounds__(128, 3) void attn_kernel()
{
    extern __shared__ float sm[];
    float* Ks = sm;                 // BK*HS  = 4096 floats (16KB)
    float* Vs = sm + BK * HS;       // BK*HS  = 4096 floats (16KB)
    float* ss = sm + 2 * BK * HS;   // BK*BQ  = 8192 floats (32KB)

    const int tid = threadIdx.x;
    const int j   = NQT - 1 - blockIdx.x;   // heavy q-tiles first
    const int sp  = blockIdx.y;     // split
    const int b   = blockIdx.z;     // batch
    const int q0  = j * BQ;
    const int q   = q0 + tid;

    const int nkt = 2 * (j + 1);    // K-tiles covering [0, BQ*(j+1))
    const int t0  = (nkt * sp) / NSPL;
    const int t1  = (nkt * (sp + 1)) / NSPL;

    const float* __restrict__ Kb = g_K + (size_t)b * SEQ * HS;
    const float* __restrict__ Vb = g_V + (size_t)b * SEQ * HS;

    // q row -> 32 packed f32x2 registers
    u64t qq[32];
    {
        const ulonglong2* Qp =
            (const ulonglong2*)(g_Q + ((size_t)b * SEQ + q) * HS);
        #pragma unroll
        for (int i = 0; i < 16; i++) {
            const ulonglong2 t = Qp[i];
            qq[2 * i]     = t.x;
            qq[2 * i + 1] = t.y;
        }
    }

    u64t o2[32];
    #pragma unroll
    for (int i = 0; i < 32; i++) o2[i] = 0ull;
    float m = -INFINITY;
    float l = 0.f;

    for (int kt = t0; kt < t1; kt++) {
        const int k0 = kt * BK;

        // ---- load K/V tiles: 1024 float4 each, 8 per thread ----
        #pragma unroll
        for (int t = tid; t < (BK * HS) / 4; t += BQ) {
            const int r = t >> 4;
            const int c = t & 15;
            ((float4*)Ks)[t] = *(const float4*)&Kb[(size_t)(k0 + r) * HS + 4 * c];
            ((float4*)Vs)[t] = *(const float4*)&Vb[(size_t)(k0 + r) * HS + 4 * c];
        }
        __syncthreads();

        // ---- score pass: 4 keys in flight, packed FMA ----
        float tmax = -INFINITY;
        for (int k = 0; k < BK; k += 4) {
            const ulonglong2* K0 = (const ulonglong2*)&Ks[(k + 0) * HS];
            const ulonglong2* K1 = (const ulonglong2*)&Ks[(k + 1) * HS];
            const ulonglong2* K2 = (const ulonglong2*)&Ks[(k + 2) * HS];
            const ulonglong2* K3 = (const ulonglong2*)&Ks[(k + 3) * HS];
            u64t a0 = 0ull, a1 = 0ull, a2 = 0ull, a3 = 0ull;
            #pragma unroll
            for (int i = 0; i < 16; i++) {
                const ulonglong2 k0v = K0[i], k1v = K1[i], k2v = K2[i], k3v = K3[i];
                a0 = fma2(qq[2 * i], k0v.x, a0); a0 = fma2(qq[2 * i + 1], k0v.y, a0);
                a1 = fma2(qq[2 * i], k1v.x, a1); a1 = fma2(qq[2 * i + 1], k1v.y, a1);
                a2 = fma2(qq[2 * i], k2v.x, a2); a2 = fma2(qq[2 * i + 1], k2v.y, a2);
                a3 = fma2(qq[2 * i], k3v.x, a3); a3 = fma2(qq[2 * i + 1], k3v.y, a3);
            }
            float lo, hi, s0, s1, s2, s3;
            upk2(a0, lo, hi); s0 = (lo + hi) * 0.125f;
            upk2(a1, lo, hi); s1 = (lo + hi) * 0.125f;
            upk2(a2, lo, hi); s2 = (lo + hi) * 0.125f;
            upk2(a3, lo, hi); s3 = (lo + hi) * 0.125f;
            if (k0 + k + 0 > q) s0 = -INFINITY;
            if (k0 + k + 1 > q) s1 = -INFINITY;
            if (k0 + k + 2 > q) s2 = -INFINITY;
            if (k0 + k + 3 > q) s3 = -INFINITY;
            ss[(k + 0) * BQ + tid] = s0;
            ss[(k + 1) * BQ + tid] = s1;
            ss[(k + 2) * BQ + tid] = s2;
            ss[(k + 3) * BQ + tid] = s3;
            tmax = fmaxf(tmax, fmaxf(fmaxf(s0, s1), fmaxf(s2, s3)));
        }

        // ---- online softmax rescale ----
        // guard: while this split has seen only masked tiles, m == -inf and
        // o == 0; exp(-inf - -inf) would be NaN. Do NOT remove the ternary.
        const float mnew = fmaxf(m, tmax);
        const float corr = (m == -INFINITY) ? 0.f : __expf(m - mnew);
        l *= corr;
        const u64t cc = pk2(corr, corr);
        #pragma unroll
        for (int i = 0; i < 32; i++) o2[i] = mul2(o2[i], cc);
        m = mnew;

        // ---- P@V accumulate, packed FMA; dual l accumulators for ILP ----
        float lacc0 = 0.f, lacc1 = 0.f;
        #pragma unroll 4
        for (int k = 0; k < BK; k++) {
            const float sval = ss[k * BQ + tid];
            // guard: fully-masked tile has m == -inf; exp(-inf - -inf) = NaN
            const float p = (sval == -INFINITY) ? 0.f : __expf(sval - m);
            if (k & 1) lacc1 += p; else lacc0 += p;
            const u64t pp = pk2(p, p);
            const ulonglong2* V2 = (const ulonglong2*)&Vs[k * HS];
            #pragma unroll
            for (int i = 0; i < 16; i++) {
                const ulonglong2 vv = V2[i];
                o2[2 * i]     = fma2(pp, vv.x, o2[2 * i]);
                o2[2 * i + 1] = fma2(pp, vv.y, o2[2 * i + 1]);
            }
        }
        l += lacc0 + lacc1;
        __syncthreads();
    }

    // ---- write partial (o_hat, m, l); STG.128 pairs for half the store issue
    const size_t qi = (size_t)b * SEQ + q;
    g_m[sp][qi] = m;
    g_l[sp][qi] = l;
    ulonglong2* op = (ulonglong2*)(g_opart +
                       ((size_t)sp * BATCH * SEQ + qi) * (size_t)HS);
    #pragma unroll
    for (int i = 0; i < 16; i++) {
        ulonglong2 v;
        v.x = o2[2 * i];
        v.y = o2[2 * i + 1];
        op[i] = v;
    }
}

// ============================================================================
// Kernel 3: combine the split-K partials and normalize.
// One thread per query row (16384 threads).
// ============================================================================
__global__ __launch_bounds__(128) void combine_kernel(float* __restrict__ out)
{
    const int idx = blockIdx.x * blockDim.x + threadIdx.x;   // query row

    float mv[NSPL], lv[NSPL];
    float M = -INFINITY;
    #pragma unroll
    for (int s = 0; s < NSPL; s++) {
        mv[s] = g_m[s][idx];
        lv[s] = g_l[s][idx];
        M = fmaxf(M, mv[s]);
    }
    float w[NSPL];
    float den = 0.f;
    #pragma unroll
    for (int s = 0; s < NSPL; s++) {
        w[s] = (mv[s] == -INFINITY) ? 0.f : __expf(mv[s] - M);
        den += w[s] * lv[s];
    }
    const float inv = 1.f / den;

    float4 acc[16];
    #pragma unroll
    for (int i = 0; i < 16; i++) acc[i] = make_float4(0.f, 0.f, 0.f, 0.f);
    #pragma unroll
    for (int s = 0; s < NSPL; s++) {
        const float a = w[s] * inv;
        const float4* p = (const float4*)(g_opart +
                            ((size_t)s * BATCH * SEQ + idx) * (size_t)HS);
        #pragma unroll
        for (int i = 0; i < 16; i++) {
            const float4 u = p[i];
            acc[i].x = fmaf(a, u.x, acc[i].x);
            acc[i].y = fmaf(a, u.y, acc[i].y);
            acc[i].z = fmaf(a, u.z, acc[i].z);
            acc[i].w = fmaf(a, u.w, acc[i].w);
        }
    }
    float4* po = (float4*)(out + (size_t)idx * HS);
    #pragma unroll
    for (int i = 0; i < 16; i++) po[i] = acc[i];
}

// ============================================================================
// Launch
// ============================================================================
extern "C" void kernel_launch(void* const* d_in, const int* in_sizes, int n_in,
                              void* d_out, int out_size)
{
    const float* x  = (const float*)d_in[0];
    const float* Wq = (const float*)d_in[1];
    const float* Wk = (const float*)d_in[2];
    const float* Wv = (const float*)d_in[3];
    float* out = (float*)d_out;

    proj_kernel<<<(BATCH * SEQ) / PBM, 256>>>(x, Wq, Wk, Wv);

    cudaFuncSetAttribute(attn_kernel,
                         cudaFuncAttributeMaxDynamicSharedMemorySize, 65536);
    dim3 agrid(NQT, NSPL, BATCH);
    attn_kernel<<<agrid, BQ, 65536>>>();

    combine_kernel<<<(BATCH * SEQ) / 128, 128>>>(out);
}